// round 1
// baseline (speedup 1.0000x reference)
#include <cuda_runtime.h>
#include <math.h>

#define D 64
#define NMAX 100000
#define EMAX 1600000

// Scratch (allocation-free rule: __device__ globals)
// g_xw:  [0]=x@W_low  [1]=x@W_high  [2]=x@W_mlp          (3 * N * 64 floats)
// g_acc: [0]=acc_low [1]=acc_high
//        [2+k]=neigh_low[k]  (k=0 homo,1 hete,2 unk)
//        [5+k]=neigh_high[k]                             (8 * N * 64 floats)
__device__ float g_xw[3ULL * NMAX * D];
__device__ float g_acc[8ULL * NMAX * D];

__device__ __forceinline__ void red4(float* a, float x, float y, float z, float w) {
    asm volatile("red.global.add.v4.f32 [%0], {%1, %2, %3, %4};"
                 :: "l"(a), "f"(x), "f"(y), "f"(z), "f"(w) : "memory");
}

__global__ void zero_kernel(int n4) {
    int i = blockIdx.x * blockDim.x + threadIdx.x;
    if (i < n4) ((float4*)g_acc)[i] = make_float4(0.f, 0.f, 0.f, 0.f);
}

// 3 fused GEMMs: one warp per row, W staged in shared (48KB).
__global__ void gemm3_kernel(const float* __restrict__ x,
                             const float* __restrict__ wl,
                             const float* __restrict__ wh,
                             const float* __restrict__ wm,
                             int n) {
    __shared__ float sW[3][D][D];
    for (int i = threadIdx.x; i < D * D; i += blockDim.x) {
        sW[0][i >> 6][i & 63] = wl[i];
        sW[1][i >> 6][i & 63] = wh[i];
        sW[2][i >> 6][i & 63] = wm[i];
    }
    __syncthreads();
    int warp = threadIdx.x >> 5, lane = threadIdx.x & 31;
    int row = blockIdx.x * 8 + warp;
    if (row >= n) return;
    float2 xv = *(const float2*)(x + (size_t)row * D + lane * 2);
    float a0 = 0.f, a1 = 0.f, b0 = 0.f, b1 = 0.f, c0 = 0.f, c1 = 0.f;
#pragma unroll
    for (int k = 0; k < D; k++) {
        float xk = __shfl_sync(0xffffffffu, (k & 1) ? xv.y : xv.x, k >> 1);
        a0 += xk * sW[0][k][lane];      a1 += xk * sW[0][k][lane + 32];
        b0 += xk * sW[1][k][lane];      b1 += xk * sW[1][k][lane + 32];
        c0 += xk * sW[2][k][lane];      c1 += xk * sW[2][k][lane + 32];
    }
    size_t nd = (size_t)n * D;
    size_t o = (size_t)row * D;
    g_xw[o + lane] = a0;               g_xw[o + lane + 32] = a1;
    g_xw[nd + o + lane] = b0;          g_xw[nd + o + lane + 32] = b1;
    g_xw[2 * nd + o + lane] = c0;      g_xw[2 * nd + o + lane + 32] = c1;
}

// Fused low+high SpMM: 16 threads per edge, float4 gather + vector red.
__global__ void spmm_kernel(const float* __restrict__ vl,
                            const float* __restrict__ vh,
                            const int* __restrict__ src,
                            const int* __restrict__ dst,
                            int e, int n) {
    int tid = blockIdx.x * blockDim.x + threadIdx.x;
    int eid = tid >> 4;
    if (eid >= e) return;
    int c = (tid & 15) << 2;
    int s = src[eid], d = dst[eid];
    float a = vl[eid], b = vh[eid];
    size_t nd = (size_t)n * D;
    float4 fl = *(const float4*)(g_xw + (size_t)s * D + c);
    float4 fh = *(const float4*)(g_xw + nd + (size_t)s * D + c);
    red4(g_acc + (size_t)d * D + c, a * fl.x, a * fl.y, a * fl.z, a * fl.w);
    red4(g_acc + nd + (size_t)d * D + c, b * fh.x, b * fh.y, b * fh.z, b * fh.w);
}

// Label-bucketed aggregation: ReLU fused into the gather of acc_low/high.
__global__ void agg_kernel(const int* __restrict__ src,
                           const int* __restrict__ dst,
                           const int* __restrict__ label,
                           int e, int n) {
    int tid = blockIdx.x * blockDim.x + threadIdx.x;
    int eid = tid >> 4;
    if (eid >= e) return;
    int c = (tid & 15) << 2;
    int s = src[eid], d = dst[eid];
    int sl = label[s], dl = label[d];
    int k = ((sl < 0) || (dl < 0)) ? 2 : ((sl != dl) ? 1 : 0);
    size_t nd = (size_t)n * D;
    float4 fl = *(const float4*)(g_acc + (size_t)s * D + c);
    float4 fh = *(const float4*)(g_acc + nd + (size_t)s * D + c);
    fl.x = fmaxf(fl.x, 0.f); fl.y = fmaxf(fl.y, 0.f);
    fl.z = fmaxf(fl.z, 0.f); fl.w = fmaxf(fl.w, 0.f);
    fh.x = fmaxf(fh.x, 0.f); fh.y = fmaxf(fh.y, 0.f);
    fh.z = fmaxf(fh.z, 0.f); fh.w = fmaxf(fh.w, 0.f);
    red4(g_acc + (size_t)(2 + k) * nd + (size_t)d * D + c, fl.x, fl.y, fl.z, fl.w);
    red4(g_acc + (size_t)(5 + k) * nd + (size_t)d * D + c, fh.x, fh.y, fh.z, fh.w);
}

// Per-node attention epilogue: warp per node.
__global__ void final_kernel(const float* __restrict__ alf, const float* __restrict__ ahf,
                             const float* __restrict__ alb, const float* __restrict__ ahb,
                             const float* __restrict__ alu, const float* __restrict__ ahu,
                             const float* __restrict__ am,  const float* __restrict__ a7,
                             float* __restrict__ out, int n) {
    __shared__ float sAtt[7][D];
    __shared__ float sA7[49];
    if (threadIdx.x < D) {
        int c = threadIdx.x;
        sAtt[0][c] = alf[c]; sAtt[1][c] = ahf[c]; sAtt[2][c] = alb[c];
        sAtt[3][c] = ahb[c]; sAtt[4][c] = alu[c]; sAtt[5][c] = ahu[c];
        sAtt[6][c] = am[c];
    }
    if (threadIdx.x < 49) sA7[threadIdx.x] = a7[threadIdx.x];
    __syncthreads();
    int warp = threadIdx.x >> 5, lane = threadIdx.x & 31;
    int node = blockIdx.x * 8 + warp;
    if (node >= n) return;
    size_t nd = (size_t)n * D;
    size_t o = (size_t)node * D + lane * 2;
    float2 b0l = *(const float2*)(g_acc + 2 * nd + o);  // homo low
    float2 b1l = *(const float2*)(g_acc + 3 * nd + o);  // hete low
    float2 b2l = *(const float2*)(g_acc + 4 * nd + o);  // unk  low
    float2 b0h = *(const float2*)(g_acc + 5 * nd + o);  // homo high
    float2 b1h = *(const float2*)(g_acc + 6 * nd + o);  // hete high
    float2 b2h = *(const float2*)(g_acc + 7 * nd + o);  // unk  high
    float2 ml  = *(const float2*)(g_xw + 2 * nd + o);   // mlp (pre-relu)
    float2 mlp;
    mlp.x = fmaxf(ml.x, 0.f); mlp.y = fmaxf(ml.y, 0.f);

    int c = lane * 2;
    float pd[7];
    pd[0] = b1l.x * sAtt[0][c] + b1l.y * sAtt[0][c + 1];
    pd[1] = b1h.x * sAtt[1][c] + b1h.y * sAtt[1][c + 1];
    pd[2] = b0l.x * sAtt[2][c] + b0l.y * sAtt[2][c + 1];
    pd[3] = b0h.x * sAtt[3][c] + b0h.y * sAtt[3][c + 1];
    pd[4] = b2l.x * sAtt[4][c] + b2l.y * sAtt[4][c + 1];
    pd[5] = b2h.x * sAtt[5][c] + b2h.y * sAtt[5][c + 1];
    pd[6] = mlp.x * sAtt[6][c] + mlp.y * sAtt[6][c + 1];
#pragma unroll
    for (int off = 16; off; off >>= 1) {
#pragma unroll
        for (int j = 0; j < 7; j++)
            pd[j] += __shfl_xor_sync(0xffffffffu, pd[j], off);
    }
    float f[7];
#pragma unroll
    for (int j = 0; j < 7; j++)
        f[j] = 1.f / (1.f + expf(-pd[j]));
    float lg[7];
    float m = -1e30f;
#pragma unroll
    for (int i = 0; i < 7; i++) {
        float s = 0.f;
#pragma unroll
        for (int j = 0; j < 7; j++) s += f[j] * sA7[j * 7 + i];
        lg[i] = s * (1.0f / 7.0f);
        m = fmaxf(m, lg[i]);
    }
    float sum = 0.f;
#pragma unroll
    for (int i = 0; i < 7; i++) { lg[i] = expf(lg[i] - m); sum += lg[i]; }
    float inv = 7.0f / sum;   // fold the final *7 into the softmax normalizer
#pragma unroll
    for (int i = 0; i < 7; i++) lg[i] *= inv;

    float2 r;
    r.x = lg[0] * b1l.x + lg[1] * b1h.x + lg[2] * b0l.x + lg[3] * b0h.x
        + lg[4] * b2l.x + lg[5] * b2h.x + lg[6] * mlp.x;
    r.y = lg[0] * b1l.y + lg[1] * b1h.y + lg[2] * b0l.y + lg[3] * b0h.y
        + lg[4] * b2l.y + lg[5] * b2h.y + lg[6] * mlp.y;
    *(float2*)(out + o) = r;
}

extern "C" void kernel_launch(void* const* d_in, const int* in_sizes, int n_in,
                              void* d_out, int out_size) {
    const float* x   = (const float*)d_in[0];
    const float* vl  = (const float*)d_in[1];
    const float* vh  = (const float*)d_in[2];
    const float* wl  = (const float*)d_in[3];
    const float* wh  = (const float*)d_in[4];
    const float* wm  = (const float*)d_in[5];
    const float* alf = (const float*)d_in[6];
    const float* ahf = (const float*)d_in[7];
    const float* alb = (const float*)d_in[8];
    const float* ahb = (const float*)d_in[9];
    const float* alu = (const float*)d_in[10];
    const float* ahu = (const float*)d_in[11];
    const float* am  = (const float*)d_in[12];
    const float* a7  = (const float*)d_in[13];
    const int* src   = (const int*)d_in[14];
    const int* dst   = (const int*)d_in[15];
    const int* lab   = (const int*)d_in[16];
    int n = in_sizes[0] / D;
    int e = in_sizes[14];
    float* out = (float*)d_out;

    int n4 = 8 * n * (D / 4);  // floats4 to zero in g_acc
    zero_kernel<<<(n4 + 255) / 256, 256>>>(n4);
    gemm3_kernel<<<(n + 7) / 8, 256>>>(x, wl, wh, wm, n);
    int et = e * 16;
    spmm_kernel<<<(et + 255) / 256, 256>>>(vl, vh, src, dst, e, n);
    agg_kernel<<<(et + 255) / 256, 256>>>(src, dst, lab, e, n);
    final_kernel<<<(n + 7) / 8, 256>>>(alf, ahf, alb, ahb, alu, ahu, am, a7, out, n);
}